// round 14
// baseline (speedup 1.0000x reference)
#include <cuda_runtime.h>
#include <cstdint>

#define NTOK   131072
#define CCH    96
#define BB     2
#define TN     128
#define NTILE  1024
#define NBLK   (BB*NTILE)      // 2048
#define NPART  1248
#define NCHUNK 8
#define NSEG   32
#define RS     132
#define R4S    (RS/4)
#define WS     100

__device__ float g_partial[(size_t)NBLK * NCHUNK * NPART];
__device__ float g_red1[NSEG * BB * NPART];
__device__ float g_red[BB * NPART];
__device__ float g_WCt[BB * 9216];     // folded (Wproj @ ctx)^T : [b][c'][o]
__device__ int   g_dummy;

typedef unsigned long long ull;

__device__ __forceinline__ ull pack2(float x, float y) {
    ull r; asm("mov.b64 %0, {%1, %2};" : "=l"(r) : "f"(x), "f"(y)); return r;
}
__device__ __forceinline__ void fma2(ull& d, ull a, ull b) {
    asm("fma.rn.f32x2 %0, %1, %2, %0;" : "+l"(d) : "l"(a), "l"(b));
}
__device__ __forceinline__ float2 unpack2(ull a) {
    float lo, hi; asm("mov.b64 {%0, %1}, %2;" : "=f"(lo), "=f"(hi) : "l"(a));
    return make_float2(lo, hi);
}

// no-op launch-slot filler (deterministic)
__global__ void noop_kernel() { if (threadIdx.x == 1024) g_dummy = 0; }

// =====================================================================
// Kernel A (= R13): 1024 thr, matrix-split k/v. Stage x -> GEMM
// (12 accs, 2 tok x 12 ch) -> exp(k)/v -> fine partials.
// =====================================================================
__global__ void __launch_bounds__(1024, 1)
kv_kernel(const float* __restrict__ x,
          const float* __restrict__ Wk, const float* __restrict__ Wv)
{
    extern __shared__ float sm[];
    float* sX  = sm;                    // [96][RS]
    float* sK  = sX + 96 * RS;
    float* sV  = sK + 96 * RS;
    float* sWk = sV + 96 * RS;          // [96][WS]
    float* sWv = sWk + 96 * WS;

    const int tile = blockIdx.x;
    const int b    = tile >> 10;
    const int n0   = (tile & (NTILE - 1)) * TN;
    const int tid  = threadIdx.x;
    const int mat  = tid >> 9;
    const int og   = (tid >> 6) & 7;
    const int tg   = tid & 63;
    const int nt   = tg * 2;

    const float* xb = x + (size_t)b * CCH * NTOK + n0;
    #pragma unroll
    for (int it = 0; it < 3; it++) {
        int i = tid + it * 1024;
        int c = i >> 5, n4 = i & 31;
        ((float4*)(sX + c * RS))[n4] = ((const float4*)(xb + (size_t)c * NTOK))[n4];
    }
    for (int i = tid; i < CCH * CCH; i += 1024) {
        int o = i / 96, c = i - o * 96;
        sWk[c * WS + o] = Wk[i];
        sWv[c * WS + o] = Wv[i];
    }
    __syncthreads();

    const float* sW = mat ? sWv : sWk;
    ull acc[12];
    #pragma unroll
    for (int j = 0; j < 12; j++) acc[j] = 0ull;
    #pragma unroll 2
    for (int c = 0; c < 96; c++) {
        float2 xv = *(const float2*)(sX + c * RS + nt);
        ull x0 = pack2(xv.x, xv.x), x1 = pack2(xv.y, xv.y);
        const ulonglong2* w4 = (const ulonglong2*)(sW + c * WS + og * 12);
        #pragma unroll
        for (int jj = 0; jj < 3; jj++) {
            ulonglong2 w = w4[jj];
            fma2(acc[jj * 4 + 0], w.x, x0); fma2(acc[jj * 4 + 1], w.x, x1);
            fma2(acc[jj * 4 + 2], w.y, x0); fma2(acc[jj * 4 + 3], w.y, x1);
        }
    }

    float* dst = mat ? sV : sK;
    #pragma unroll
    for (int jj = 0; jj < 3; jj++)
        #pragma unroll
        for (int s = 0; s < 2; s++) {
            float2 a0 = unpack2(acc[jj * 4 + s * 2 + 0]);
            float2 a1 = unpack2(acc[jj * 4 + s * 2 + 1]);
            int o = og * 12 + jj * 4 + s * 2;
            if (mat == 0) {
                *(float2*)(dst + o * RS + nt)       = make_float2(__expf(a0.x), __expf(a1.x));
                *(float2*)(dst + (o + 1) * RS + nt) = make_float2(__expf(a0.y), __expf(a1.y));
            } else {
                *(float2*)(dst + o * RS + nt)       = make_float2(a0.x, a1.x);
                *(float2*)(dst + (o + 1) * RS + nt) = make_float2(a0.y, a1.y);
            }
        }
    __syncthreads();

    if (tid < 576) {
        int chunk = tid & 7, bidx = tid >> 3;
        int h = bidx / 9, r = bidx - h * 9, db = r / 3, eb = r - db * 3;
        const float4* pk0 = (const float4*)(sK + (h * 12 + db * 4) * RS) + chunk * 4;
        const float4* pv0 = (const float4*)(sV + (h * 12 + eb * 4) * RS) + chunk * 4;
        ull a2[16];
        #pragma unroll
        for (int i = 0; i < 16; i++) a2[i] = 0ull;
        #pragma unroll
        for (int t = 0; t < 4; t++) {
            float4 K[4], V[4];
            #pragma unroll
            for (int i = 0; i < 4; i++) { K[i] = pk0[i * R4S + t]; V[i] = pv0[i * R4S + t]; }
            ull Kxy[4], Kzw[4], Vxy[4], Vzw[4];
            #pragma unroll
            for (int i = 0; i < 4; i++) {
                Kxy[i] = pack2(K[i].x, K[i].y); Kzw[i] = pack2(K[i].z, K[i].w);
                Vxy[i] = pack2(V[i].x, V[i].y); Vzw[i] = pack2(V[i].z, V[i].w);
            }
            #pragma unroll
            for (int i = 0; i < 4; i++)
                #pragma unroll
                for (int j = 0; j < 4; j++) {
                    fma2(a2[i * 4 + j], Kxy[i], Vxy[j]);
                    fma2(a2[i * 4 + j], Kzw[i], Vzw[j]);
                }
        }
        float* po = g_partial + ((size_t)tile * NCHUNK + chunk) * NPART;
        #pragma unroll
        for (int i = 0; i < 4; i++)
            #pragma unroll
            for (int j = 0; j < 4; j++) {
                float2 v = unpack2(a2[i * 4 + j]);
                po[h * 144 + (db * 4 + i) * 12 + eb * 4 + j] = v.x + v.y;
            }
    } else if (tid < 768) {
        int s = tid - 576;
        int chunk = s & 7, ci = s >> 3;
        float a[4] = {0.f, 0.f, 0.f, 0.f};
        #pragma unroll
        for (int t = 0; t < 4; t++)
            #pragma unroll
            for (int i = 0; i < 4; i++) {
                float4 K = ((const float4*)(sK + (ci * 4 + i) * RS))[chunk * 4 + t];
                a[i] += K.x + K.y + K.z + K.w;
            }
        float* po = g_partial + ((size_t)tile * NCHUNK + chunk) * NPART;
        #pragma unroll
        for (int i = 0; i < 4; i++) po[1152 + ci * 4 + i] = a[i];
    }
}

// ===== stage-1 reduce =====
__global__ void red1_kernel()
{
    int idx = blockIdx.x * 256 + threadIdx.x;
    int b = blockIdx.y, seg = blockIdx.z;
    if (idx >= NPART) return;
    float a = 0.f;
    const float* p = g_partial +
        ((size_t)b * NTILE * NCHUNK + (size_t)seg * (NTILE * NCHUNK / NSEG)) * NPART + idx;
    #pragma unroll 8
    for (int t = 0; t < NTILE * NCHUNK / NSEG; t++) a += p[(size_t)t * NPART];
    g_red1[(seg * BB + b) * NPART + idx] = a;
}

// ===== stage-2 reduce =====
__global__ void red2_kernel()
{
    int gid = blockIdx.x * 256 + threadIdx.x;
    if (gid >= BB * NPART) return;
    int b = gid / NPART, idx = gid - b * NPART;
    float a = 0.f;
    #pragma unroll
    for (int s = 0; s < NSEG; s++) a += g_red1[(s * BB + b) * NPART + idx];
    g_red[gid] = a;
}

// ===== WC^T fold =====
__global__ void ctx2_kernel(const float* __restrict__ Wproj)
{
    int gid = blockIdx.x * 256 + threadIdx.x;
    if (gid >= BB * 9216) return;
    int b = gid / 9216;
    int r = gid - b * 9216;
    int o = r / 96, cp = r - o * 96;
    int h = cp / 12;
    const float* kv = g_red + b * NPART + h * 144 + (cp - h * 12) * 12;
    const float* wp = Wproj + o * 96 + h * 12;
    float a = 0.f;
    #pragma unroll
    for (int e = 0; e < 12; e++) a += wp[e] * kv[e];
    g_WCt[(b * 96 + cp) * 96 + o] = a / g_red[b * NPART + 1152 + cp];
}

// =====================================================================
// Kernel C: 512 thr, 2 CTAs/SM (8 warps/SMSP), smem weights.
// stage x + Wq -> q GEMM (12 accs) -> reload sW=WCt + softmax ->
// p in-place -> WC GEMM -> out. 2 tok x 12 ch per thread.
// =====================================================================
__global__ void __launch_bounds__(512, 2)
out2_kernel(const float* __restrict__ x, const float* __restrict__ Wq,
            float* __restrict__ out)
{
    extern __shared__ float sm[];
    float* sX = sm;                 // [96][RS]: x, then p in-place
    float* sW = sX + 96 * RS;       // [96][WS]: Wq, then WCt

    const int tile = blockIdx.x;
    const int b    = tile >> 10;
    const int n0   = (tile & (NTILE - 1)) * TN;
    const int tid  = threadIdx.x;
    const int tg   = tid & 63;
    const int og   = tid >> 6;
    const int nt   = tg * 2;

    const float* xb = x + (size_t)b * CCH * NTOK + n0;
    #pragma unroll
    for (int it = 0; it < 6; it++) {
        int i = tid + it * 512;
        int c = i >> 5, n4 = i & 31;
        ((float4*)(sX + c * RS))[n4] = ((const float4*)(xb + (size_t)c * NTOK))[n4];
    }
    for (int i = tid; i < CCH * CCH; i += 512) {
        int o = i / 96, c = i - o * 96;
        sW[c * WS + o] = Wq[i];
    }
    __syncthreads();

    // q GEMM: 12 accs (2 tok x 12 ch)
    ull aq[12];
    #pragma unroll
    for (int j = 0; j < 12; j++) aq[j] = 0ull;
    #pragma unroll 2
    for (int c = 0; c < 96; c++) {
        float2 xv = *(const float2*)(sX + c * RS + nt);
        ull x0 = pack2(xv.x, xv.x), x1 = pack2(xv.y, xv.y);
        const ulonglong2* w4 = (const ulonglong2*)(sW + c * WS + og * 12);
        #pragma unroll
        for (int jj = 0; jj < 3; jj++) {
            ulonglong2 w = w4[jj];
            fma2(aq[jj * 4 + 0], w.x, x0); fma2(aq[jj * 4 + 1], w.x, x1);
            fma2(aq[jj * 4 + 2], w.y, x0); fma2(aq[jj * 4 + 3], w.y, x1);
        }
    }
    __syncthreads();    // all reads of x (sX) and Wq (sW) complete

    // reload sW with WCt while softmax proceeds
    const float* wct = g_WCt + b * 9216;
    for (int i = tid; i < CCH * CCH; i += 512) {
        int cp = i / 96, o = i - cp * 96;
        sW[cp * WS + o] = wct[i];
    }

    // softmax over head dim per token; write p into sX in-place
    #pragma unroll
    for (int t = 0; t < 2; t++) {
        float qv[12];
        #pragma unroll
        for (int jj = 0; jj < 3; jj++)
            #pragma unroll
            for (int s = 0; s < 2; s++) {
                float2 v = unpack2(aq[jj * 4 + s * 2 + t]);
                qv[jj * 4 + s * 2]     = v.x;
                qv[jj * 4 + s * 2 + 1] = v.y;
            }
        float m = qv[0];
        #pragma unroll
        for (int i = 1; i < 12; i++) m = fmaxf(m, qv[i]);
        float p[12]; float sum = 0.f;
        #pragma unroll
        for (int i = 0; i < 12; i++) { p[i] = __expf(qv[i] - m); sum += p[i]; }
        float inv = 1.f / sum;
        #pragma unroll
        for (int i = 0; i < 12; i++)
            sX[(og * 12 + i) * RS + nt + t] = p[i] * inv;
    }
    __syncthreads();    // p tile + WCt load complete

    // WC GEMM
    ull ap[12];
    #pragma unroll
    for (int j = 0; j < 12; j++) ap[j] = 0ull;
    #pragma unroll 2
    for (int c = 0; c < 96; c++) {
        float2 pv = *(const float2*)(sX + c * RS + nt);
        ull x0 = pack2(pv.x, pv.x), x1 = pack2(pv.y, pv.y);
        const ulonglong2* w4 = (const ulonglong2*)(sW + c * WS + og * 12);
        #pragma unroll
        for (int jj = 0; jj < 3; jj++) {
            ulonglong2 w = w4[jj];
            fma2(ap[jj * 4 + 0], w.x, x0); fma2(ap[jj * 4 + 1], w.x, x1);
            fma2(ap[jj * 4 + 2], w.y, x0); fma2(ap[jj * 4 + 3], w.y, x1);
        }
    }

    float* ob = out + (size_t)b * CCH * NTOK + n0 + nt;
    #pragma unroll
    for (int jj = 0; jj < 3; jj++)
        #pragma unroll
        for (int s = 0; s < 2; s++) {
            float2 a0 = unpack2(ap[jj * 4 + s * 2 + 0]);   // token nt
            float2 a1 = unpack2(ap[jj * 4 + s * 2 + 1]);   // token nt+1
            int o = og * 12 + jj * 4 + s * 2;
            *(float2*)(ob + (size_t)o * NTOK)       = make_float2(a0.x, a1.x);
            *(float2*)(ob + (size_t)(o + 1) * NTOK) = make_float2(a0.y, a1.y);
        }
}

extern "C" void kernel_launch(void* const* d_in, const int* in_sizes, int n_in,
                              void* d_out, int out_size)
{
    const float* x  = (const float*)d_in[0];
    const float* Wq = (const float*)d_in[1];
    const float* Wk = (const float*)d_in[2];
    const float* Wv = (const float*)d_in[3];
    const float* Wp = (const float*)d_in[4];
    float* out = (float*)d_out;

    const size_t smA = (size_t)(3 * 96 * RS + 2 * 96 * WS) * sizeof(float);   // 228,864 B
    const size_t smC = (size_t)(96 * RS + 96 * WS) * sizeof(float);           //  89,088 B
    cudaFuncSetAttribute(kv_kernel,   cudaFuncAttributeMaxDynamicSharedMemorySize, (int)smA);
    cudaFuncSetAttribute(out2_kernel, cudaFuncAttributeMaxDynamicSharedMemorySize, (int)smC);

    // 3 no-op fillers so kv_kernel sits in the profiler's launch slot (#4)
    noop_kernel<<<1, 32>>>();
    noop_kernel<<<1, 32>>>();
    noop_kernel<<<1, 32>>>();
    kv_kernel<<<NBLK, 1024, smA>>>(x, Wk, Wv);
    red1_kernel<<<dim3(5, BB, NSEG), 256>>>();
    red2_kernel<<<(BB * NPART + 255) / 256, 256>>>();
    ctx2_kernel<<<(BB * 9216 + 255) / 256, 256>>>(Wp);
    out2_kernel<<<NBLK, 512, smC>>>(x, Wq, out);
}

// round 16
// speedup vs baseline: 1.1753x; 1.1753x over previous
#include <cuda_runtime.h>
#include <cstdint>

#define NTOK   131072
#define CCH    96
#define BB     2
#define TN     128
#define NTILE  1024
#define NBLK   (BB*NTILE)      // 2048
#define NPART  1248
#define NSEG   32
#define RSK    128             // kv smem row stride (512B aligned rows)
#define R4K    32
#define RSO    132             // out2 smem row stride
#define WS     100

__device__ float g_partial[(size_t)NBLK * NPART];   // ~10 MB
__device__ float g_red1[NSEG * BB * NPART];
__device__ float g_red[BB * NPART];
__device__ float g_WCt[BB * 9216];     // folded (Wproj @ ctx)^T : [b][c'][o]
__device__ int   g_dummy;

typedef unsigned long long ull;

__device__ __forceinline__ ull pack2(float x, float y) {
    ull r; asm("mov.b64 %0, {%1, %2};" : "=l"(r) : "f"(x), "f"(y)); return r;
}
__device__ __forceinline__ void fma2(ull& d, ull a, ull b) {
    asm("fma.rn.f32x2 %0, %1, %2, %0;" : "+l"(d) : "l"(a), "l"(b));
}
__device__ __forceinline__ float2 unpack2(ull a) {
    float lo, hi; asm("mov.b64 {%0, %1}, %2;" : "=f"(lo), "=f"(hi) : "l"(a));
    return make_float2(lo, hi);
}

__global__ void noop_kernel() { if (threadIdx.x == 1024) g_dummy = 0; }

// =====================================================================
// Kernel A: 512 thr, matrix-split k/v, 4 tok x 12 ch per thread.
// stage x -> GEMM (24 accs) -> exp(k)/v -> warp-cooperative partials
// (coalesced loads + shfl-tree reduce).
// =====================================================================
__global__ void __launch_bounds__(512, 1)
kv_kernel(const float* __restrict__ x,
          const float* __restrict__ Wk, const float* __restrict__ Wv)
{
    extern __shared__ float sm[];
    float* sX  = sm;                    // [96][RSK]
    float* sK  = sX + 96 * RSK;
    float* sV  = sK + 96 * RSK;
    float* sWk = sV + 96 * RSK;         // [96][WS]
    float* sWv = sWk + 96 * WS;

    const int tile = blockIdx.x;
    const int b    = tile >> 10;
    const int n0   = (tile & (NTILE - 1)) * TN;
    const int tid  = threadIdx.x;
    const int mat  = tid >> 8;
    const int og   = (tid >> 5) & 7;
    const int tg   = tid & 31;
    const int nt   = tg * 4;
    const int wid  = tid >> 5;
    const int lane = tid & 31;

    // stage x (3072 float4 over 512 threads) + both weights transposed
    const float* xb = x + (size_t)b * CCH * NTOK + n0;
    #pragma unroll
    for (int it = 0; it < 6; it++) {
        int i = tid + it * 512;
        int c = i >> 5, n4 = i & 31;
        ((float4*)(sX + c * RSK))[n4] = ((const float4*)(xb + (size_t)c * NTOK))[n4];
    }
    for (int i = tid; i < CCH * CCH; i += 512) {
        int o = i / 96, c = i - o * 96;
        sWk[c * WS + o] = Wk[i];
        sWv[c * WS + o] = Wv[i];
    }
    __syncthreads();

    // GEMM for my matrix: 24 accs (4 tok x 12 ch)
    const float* sW = mat ? sWv : sWk;
    ull acc[24];
    #pragma unroll
    for (int j = 0; j < 24; j++) acc[j] = 0ull;
    #pragma unroll 2
    for (int c = 0; c < 96; c++) {
        float4 xv = *(const float4*)(sX + c * RSK + nt);
        ull x0 = pack2(xv.x, xv.x), x1 = pack2(xv.y, xv.y);
        ull x2 = pack2(xv.z, xv.z), x3 = pack2(xv.w, xv.w);
        const ulonglong2* w4 = (const ulonglong2*)(sW + c * WS + og * 12);
        #pragma unroll
        for (int jj = 0; jj < 3; jj++) {
            ulonglong2 w = w4[jj];
            fma2(acc[jj * 8 + 0], w.x, x0); fma2(acc[jj * 8 + 1], w.x, x1);
            fma2(acc[jj * 8 + 2], w.x, x2); fma2(acc[jj * 8 + 3], w.x, x3);
            fma2(acc[jj * 8 + 4], w.y, x0); fma2(acc[jj * 8 + 5], w.y, x1);
            fma2(acc[jj * 8 + 6], w.y, x2); fma2(acc[jj * 8 + 7], w.y, x3);
        }
    }

    // epilogue: exp(k) -> sK (mat 0), v -> sV (mat 1); float4 rows
    float* dst = mat ? sV : sK;
    #pragma unroll
    for (int jj = 0; jj < 3; jj++)
        #pragma unroll
        for (int s = 0; s < 2; s++) {
            float2 v0 = unpack2(acc[jj * 8 + s * 4 + 0]);
            float2 v1 = unpack2(acc[jj * 8 + s * 4 + 1]);
            float2 v2 = unpack2(acc[jj * 8 + s * 4 + 2]);
            float2 v3 = unpack2(acc[jj * 8 + s * 4 + 3]);
            int o = og * 12 + jj * 4 + s * 2;
            if (mat == 0) {
                *(float4*)(dst + o * RSK + nt) =
                    make_float4(__expf(v0.x), __expf(v1.x), __expf(v2.x), __expf(v3.x));
                *(float4*)(dst + (o + 1) * RSK + nt) =
                    make_float4(__expf(v0.y), __expf(v1.y), __expf(v2.y), __expf(v3.y));
            } else {
                *(float4*)(dst + o * RSK + nt)       = make_float4(v0.x, v1.x, v2.x, v3.x);
                *(float4*)(dst + (o + 1) * RSK + nt) = make_float4(v0.y, v1.y, v2.y, v3.y);
            }
        }
    __syncthreads();

    // warp-cooperative partials: 72 KV blocks + 24 sumK tasks (96 total)
    float* po = g_partial + (size_t)tile * NPART;
    for (int task = wid; task < 96; task += 16) {
        if (task < 72) {
            int h = task / 9, r = task - h * 9, db = r / 3, eb = r - db * 3;
            const float4* pk0 = (const float4*)(sK + (h * 12 + db * 4) * RSK);
            const float4* pv0 = (const float4*)(sV + (h * 12 + eb * 4) * RSK);
            float4 K[4], V[4];
            #pragma unroll
            for (int i = 0; i < 4; i++) {
                K[i] = pk0[i * R4K + lane];     // coalesced: lane = token quad
                V[i] = pv0[i * R4K + lane];
            }
            ull a2[16];
            #pragma unroll
            for (int i = 0; i < 16; i++) a2[i] = 0ull;
            ull Kxy[4], Kzw[4], Vxy[4], Vzw[4];
            #pragma unroll
            for (int i = 0; i < 4; i++) {
                Kxy[i] = pack2(K[i].x, K[i].y); Kzw[i] = pack2(K[i].z, K[i].w);
                Vxy[i] = pack2(V[i].x, V[i].y); Vzw[i] = pack2(V[i].z, V[i].w);
            }
            #pragma unroll
            for (int i = 0; i < 4; i++)
                #pragma unroll
                for (int j = 0; j < 4; j++) {
                    fma2(a2[i * 4 + j], Kxy[i], Vxy[j]);
                    fma2(a2[i * 4 + j], Kzw[i], Vzw[j]);
                }
            float s[16];
            #pragma unroll
            for (int m = 0; m < 16; m++) {
                float2 v = unpack2(a2[m]);
                s[m] = v.x + v.y;
            }
            #pragma unroll
            for (int off = 16; off > 0; off >>= 1)
                #pragma unroll
                for (int m = 0; m < 16; m++)
                    s[m] += __shfl_down_sync(0xffffffffu, s[m], off);
            if (lane == 0) {
                #pragma unroll
                for (int i = 0; i < 4; i++)
                    #pragma unroll
                    for (int j = 0; j < 4; j++)
                        po[h * 144 + (db * 4 + i) * 12 + eb * 4 + j] = s[i * 4 + j];
            }
        } else {
            int ci = task - 72;     // ci 0..23: channels ci*4 .. ci*4+3
            float a[4];
            #pragma unroll
            for (int i = 0; i < 4; i++) {
                float4 K = ((const float4*)(sK + (ci * 4 + i) * RSK))[lane];
                a[i] = K.x + K.y + K.z + K.w;
            }
            #pragma unroll
            for (int off = 16; off > 0; off >>= 1)
                #pragma unroll
                for (int i = 0; i < 4; i++)
                    a[i] += __shfl_down_sync(0xffffffffu, a[i], off);
            if (lane == 0) {
                #pragma unroll
                for (int i = 0; i < 4; i++) po[1152 + ci * 4 + i] = a[i];
            }
        }
    }
}

// ===== stage-1 reduce: 32 segments of 32 tiles per batch =====
__global__ void red1_kernel()
{
    int idx = blockIdx.x * 256 + threadIdx.x;
    int b = blockIdx.y, seg = blockIdx.z;
    if (idx >= NPART) return;
    float a = 0.f;
    const float* p = g_partial +
        ((size_t)b * NTILE + (size_t)seg * (NTILE / NSEG)) * NPART + idx;
    #pragma unroll 8
    for (int t = 0; t < NTILE / NSEG; t++) a += p[(size_t)t * NPART];
    g_red1[(seg * BB + b) * NPART + idx] = a;
}

// ===== stage-2 reduce (fixed order) =====
__global__ void red2_kernel()
{
    int gid = blockIdx.x * 256 + threadIdx.x;
    if (gid >= BB * NPART) return;
    int b = gid / NPART, idx = gid - b * NPART;
    float a = 0.f;
    #pragma unroll
    for (int s = 0; s < NSEG; s++) a += g_red1[(s * BB + b) * NPART + idx];
    g_red[gid] = a;
}

// ===== WC^T fold =====
__global__ void ctx2_kernel(const float* __restrict__ Wproj)
{
    int gid = blockIdx.x * 256 + threadIdx.x;
    if (gid >= BB * 9216) return;
    int b = gid / 9216;
    int r = gid - b * 9216;
    int o = r / 96, cp = r - o * 96;
    int h = cp / 12;
    const float* kv = g_red + b * NPART + h * 144 + (cp - h * 12) * 12;
    const float* wp = Wproj + o * 96 + h * 12;
    float a = 0.f;
    #pragma unroll
    for (int e = 0; e < 12; e++) a += wp[e] * kv[e];
    g_WCt[(b * 96 + cp) * 96 + o] = a / g_red[b * NPART + 1152 + cp];
}

// =====================================================================
// Kernel C (= R13): 256 thr, 2 CTAs/SM. stage x + Wq -> q GEMM (24 accs)
// -> reload sW=WCt + softmax -> p in-place -> WC GEMM -> out.
// =====================================================================
__global__ void __launch_bounds__(256, 2)
out2_kernel(const float* __restrict__ x, const float* __restrict__ Wq,
            float* __restrict__ out)
{
    extern __shared__ float sm[];
    float* sX = sm;                 // [96][RSO]: x, then p in-place
    float* sW = sX + 96 * RSO;      // [96][WS]: Wq, then WCt

    const int tile = blockIdx.x;
    const int b    = tile >> 10;
    const int n0   = (tile & (NTILE - 1)) * TN;
    const int tid  = threadIdx.x;
    const int tg   = tid & 31;
    const int og   = tid >> 5;
    const int nt   = tg * 4;

    const float* xb = x + (size_t)b * CCH * NTOK + n0;
    for (int i = tid; i < CCH * (TN / 4); i += 256) {
        int c = i >> 5, n4 = i & 31;
        ((float4*)(sX + c * RSO))[n4] = ((const float4*)(xb + (size_t)c * NTOK))[n4];
    }
    for (int i = tid; i < CCH * CCH; i += 256) {
        int o = i / 96, c = i - o * 96;
        sW[c * WS + o] = Wq[i];
    }
    __syncthreads();

    ull aq[24];
    #pragma unroll
    for (int j = 0; j < 24; j++) aq[j] = 0ull;
    #pragma unroll 2
    for (int c = 0; c < 96; c++) {
        float4 xv = *(const float4*)(sX + c * RSO + nt);
        ull x0 = pack2(xv.x, xv.x), x1 = pack2(xv.y, xv.y);
        ull x2 = pack2(xv.z, xv.z), x3 = pack2(xv.w, xv.w);
        const ulonglong2* w4 = (const ulonglong2*)(sW + c * WS + og * 12);
        #pragma unroll
        for (int jj = 0; jj < 3; jj++) {
            ulonglong2 w = w4[jj];
            fma2(aq[jj * 8 + 0], w.x, x0); fma2(aq[jj * 8 + 1], w.x, x1);
            fma2(aq[jj * 8 + 2], w.x, x2); fma2(aq[jj * 8 + 3], w.x, x3);
            fma2(aq[jj * 8 + 4], w.y, x0); fma2(aq[jj * 8 + 5], w.y, x1);
            fma2(aq[jj * 8 + 6], w.y, x2); fma2(aq[jj * 8 + 7], w.y, x3);
        }
    }
    __syncthreads();    // all reads of x (sX) and Wq (sW) complete

    const float* wct = g_WCt + b * 9216;
    for (int i = tid; i < CCH * CCH; i += 256) {
        int cp = i / 96, o = i - cp * 96;
        sW[cp * WS + o] = wct[i];
    }

    #pragma unroll
    for (int t = 0; t < 4; t++) {
        float qv[12];
        #pragma unroll
        for (int jj = 0; jj < 3; jj++)
            #pragma unroll
            for (int s = 0; s < 2; s++) {
                float2 v = unpack2(aq[jj * 8 + s * 4 + t]);
                qv[jj * 4 + s * 2]     = v.x;
                qv[jj * 4 + s * 2 + 1] = v.y;
            }
        float m = qv[0];
        #pragma unroll
        for (int i = 1; i < 12; i++) m = fmaxf(m, qv[i]);
        float p[12]; float sum = 0.f;
        #pragma unroll
        for (int i = 0; i < 12; i++) { p[i] = __expf(qv[i] - m); sum += p[i]; }
        float inv = 1.f / sum;
        #pragma unroll
        for (int i = 0; i < 12; i++)
            sX[(og * 12 + i) * RSO + nt + t] = p[i] * inv;
    }
    __syncthreads();    // p tile + WCt load complete

    ull ap[24];
    #pragma unroll
    for (int j = 0; j < 24; j++) ap[j] = 0ull;
    #pragma unroll 2
    for (int c = 0; c < 96; c++) {
        float4 pv = *(const float4*)(sX + c * RSO + nt);
        ull x0 = pack2(pv.x, pv.x), x1 = pack2(pv.y, pv.y);
        ull x2 = pack2(pv.z, pv.z), x3 = pack2(pv.w, pv.w);
        const ulonglong2* w4 = (const ulonglong2*)(sW + c * WS + og * 12);
        #pragma unroll
        for (int jj = 0; jj < 3; jj++) {
            ulonglong2 w = w4[jj];
            fma2(ap[jj * 8 + 0], w.x, x0); fma2(ap[jj * 8 + 1], w.x, x1);
            fma2(ap[jj * 8 + 2], w.x, x2); fma2(ap[jj * 8 + 3], w.x, x3);
            fma2(ap[jj * 8 + 4], w.y, x0); fma2(ap[jj * 8 + 5], w.y, x1);
            fma2(ap[jj * 8 + 6], w.y, x2); fma2(ap[jj * 8 + 7], w.y, x3);
        }
    }

    float* ob = out + (size_t)b * CCH * NTOK + n0 + nt;
    #pragma unroll
    for (int jj = 0; jj < 3; jj++)
        #pragma unroll
        for (int s = 0; s < 2; s++) {
            float2 v0 = unpack2(ap[jj * 8 + s * 4 + 0]);
            float2 v1 = unpack2(ap[jj * 8 + s * 4 + 1]);
            float2 v2 = unpack2(ap[jj * 8 + s * 4 + 2]);
            float2 v3 = unpack2(ap[jj * 8 + s * 4 + 3]);
            int o = og * 12 + jj * 4 + s * 2;
            *(float4*)(ob + (size_t)o * NTOK)       = make_float4(v0.x, v1.x, v2.x, v3.x);
            *(float4*)(ob + (size_t)(o + 1) * NTOK) = make_float4(v0.y, v1.y, v2.y, v3.y);
        }
}

extern "C" void kernel_launch(void* const* d_in, const int* in_sizes, int n_in,
                              void* d_out, int out_size)
{
    const float* x  = (const float*)d_in[0];
    const float* Wq = (const float*)d_in[1];
    const float* Wk = (const float*)d_in[2];
    const float* Wv = (const float*)d_in[3];
    const float* Wp = (const float*)d_in[4];
    float* out = (float*)d_out;

    const size_t smA = (size_t)(3 * 96 * RSK + 2 * 96 * WS) * sizeof(float);   // 224,256 B
    const size_t smC = (size_t)(96 * RSO + 96 * WS) * sizeof(float);           //  89,088 B
    cudaFuncSetAttribute(kv_kernel,   cudaFuncAttributeMaxDynamicSharedMemorySize, (int)smA);
    cudaFuncSetAttribute(out2_kernel, cudaFuncAttributeMaxDynamicSharedMemorySize, (int)smC);

    // keep kv_kernel in the profiler's launch slot (#4)
    noop_kernel<<<1, 32>>>();
    noop_kernel<<<1, 32>>>();
    noop_kernel<<<1, 32>>>();
    kv_kernel<<<NBLK, 512, smA>>>(x, Wk, Wv);
    red1_kernel<<<dim3(5, BB, NSEG), 256>>>();
    red2_kernel<<<(BB * NPART + 255) / 256, 256>>>();
    ctx2_kernel<<<(BB * 9216 + 255) / 256, 256>>>(Wp);
    out2_kernel<<<NBLK, 256, smC>>>(x, Wq, out);
}

// round 17
// speedup vs baseline: 1.2479x; 1.0618x over previous
#include <cuda_runtime.h>
#include <cstdint>

#define NTOK   131072
#define CCH    96
#define BB     2
#define TN     128
#define NTILE  1024
#define NBLK   (BB*NTILE)      // 2048
#define NPART  1248
#define NSEG   32
#define RSK    128             // kv smem row stride (512B aligned rows)
#define R4K    32
#define RSO    132             // out2 smem row stride
#define WS     100

__device__ float g_partial[(size_t)NBLK * NPART];   // ~10 MB
__device__ float g_red1[NSEG * BB * NPART];
__device__ float g_red[BB * NPART];
__device__ float g_WCt[BB * 9216];     // folded (Wproj @ ctx)^T : [b][c'][o]
__device__ int   g_dummy;

typedef unsigned long long ull;

__device__ __forceinline__ ull pack2(float x, float y) {
    ull r; asm("mov.b64 %0, {%1, %2};" : "=l"(r) : "f"(x), "f"(y)); return r;
}
__device__ __forceinline__ void fma2(ull& d, ull a, ull b) {
    asm("fma.rn.f32x2 %0, %1, %2, %0;" : "+l"(d) : "l"(a), "l"(b));
}
__device__ __forceinline__ float2 unpack2(ull a) {
    float lo, hi; asm("mov.b64 {%0, %1}, %2;" : "=f"(lo), "=f"(hi) : "l"(a));
    return make_float2(lo, hi);
}

__global__ void noop_kernel() { if (threadIdx.x == 1024) g_dummy = 0; }

// =====================================================================
// Kernel A: 512 thr, matrix-split k/v, 4 tok x 12 ch per thread.
// stage x -> GEMM (24 accs) -> exp(k)/v -> warp-coop partials with
// value-halving butterfly reduction (16 shfl per 16-value task).
// =====================================================================
__global__ void __launch_bounds__(512, 1)
kv_kernel(const float* __restrict__ x,
          const float* __restrict__ Wk, const float* __restrict__ Wv)
{
    extern __shared__ float sm[];
    float* sX  = sm;                    // [96][RSK]
    float* sK  = sX + 96 * RSK;
    float* sV  = sK + 96 * RSK;
    float* sWk = sV + 96 * RSK;         // [96][WS]
    float* sWv = sWk + 96 * WS;

    const int tile = blockIdx.x;
    const int b    = tile >> 10;
    const int n0   = (tile & (NTILE - 1)) * TN;
    const int tid  = threadIdx.x;
    const int mat  = tid >> 8;
    const int og   = (tid >> 5) & 7;
    const int tg   = tid & 31;
    const int nt   = tg * 4;
    const int wid  = tid >> 5;
    const int lane = tid & 31;

    const float* xb = x + (size_t)b * CCH * NTOK + n0;
    #pragma unroll
    for (int it = 0; it < 6; it++) {
        int i = tid + it * 512;
        int c = i >> 5, n4 = i & 31;
        ((float4*)(sX + c * RSK))[n4] = ((const float4*)(xb + (size_t)c * NTOK))[n4];
    }
    for (int i = tid; i < CCH * CCH; i += 512) {
        int o = i / 96, c = i - o * 96;
        sWk[c * WS + o] = Wk[i];
        sWv[c * WS + o] = Wv[i];
    }
    __syncthreads();

    // GEMM for my matrix: 24 accs (4 tok x 12 ch)
    const float* sW = mat ? sWv : sWk;
    ull acc[24];
    #pragma unroll
    for (int j = 0; j < 24; j++) acc[j] = 0ull;
    #pragma unroll 2
    for (int c = 0; c < 96; c++) {
        float4 xv = *(const float4*)(sX + c * RSK + nt);
        ull x0 = pack2(xv.x, xv.x), x1 = pack2(xv.y, xv.y);
        ull x2 = pack2(xv.z, xv.z), x3 = pack2(xv.w, xv.w);
        const ulonglong2* w4 = (const ulonglong2*)(sW + c * WS + og * 12);
        #pragma unroll
        for (int jj = 0; jj < 3; jj++) {
            ulonglong2 w = w4[jj];
            fma2(acc[jj * 8 + 0], w.x, x0); fma2(acc[jj * 8 + 1], w.x, x1);
            fma2(acc[jj * 8 + 2], w.x, x2); fma2(acc[jj * 8 + 3], w.x, x3);
            fma2(acc[jj * 8 + 4], w.y, x0); fma2(acc[jj * 8 + 5], w.y, x1);
            fma2(acc[jj * 8 + 6], w.y, x2); fma2(acc[jj * 8 + 7], w.y, x3);
        }
    }

    // epilogue: exp(k) -> sK (mat 0), v -> sV (mat 1)
    float* dst = mat ? sV : sK;
    #pragma unroll
    for (int jj = 0; jj < 3; jj++)
        #pragma unroll
        for (int s = 0; s < 2; s++) {
            float2 v0 = unpack2(acc[jj * 8 + s * 4 + 0]);
            float2 v1 = unpack2(acc[jj * 8 + s * 4 + 1]);
            float2 v2 = unpack2(acc[jj * 8 + s * 4 + 2]);
            float2 v3 = unpack2(acc[jj * 8 + s * 4 + 3]);
            int o = og * 12 + jj * 4 + s * 2;
            if (mat == 0) {
                *(float4*)(dst + o * RSK + nt) =
                    make_float4(__expf(v0.x), __expf(v1.x), __expf(v2.x), __expf(v3.x));
                *(float4*)(dst + (o + 1) * RSK + nt) =
                    make_float4(__expf(v0.y), __expf(v1.y), __expf(v2.y), __expf(v3.y));
            } else {
                *(float4*)(dst + o * RSK + nt)       = make_float4(v0.x, v1.x, v2.x, v3.x);
                *(float4*)(dst + (o + 1) * RSK + nt) = make_float4(v0.y, v1.y, v2.y, v3.y);
            }
        }
    __syncthreads();

    // warp-cooperative partials: 72 KV + 24 sumK tasks over 16 warps
    float* po = g_partial + (size_t)tile * NPART;
    for (int task = wid; task < 96; task += 16) {
        if (task < 72) {
            int h = task / 9, r = task - h * 9, db = r / 3, eb = r - db * 3;
            const float4* pk0 = (const float4*)(sK + (h * 12 + db * 4) * RSK);
            const float4* pv0 = (const float4*)(sV + (h * 12 + eb * 4) * RSK);
            float4 K[4], V[4];
            #pragma unroll
            for (int i = 0; i < 4; i++) {
                K[i] = pk0[i * R4K + lane];     // coalesced: lane = token quad
                V[i] = pv0[i * R4K + lane];
            }
            ull a2[16];
            #pragma unroll
            for (int i = 0; i < 16; i++) a2[i] = 0ull;
            ull Kxy[4], Kzw[4], Vxy[4], Vzw[4];
            #pragma unroll
            for (int i = 0; i < 4; i++) {
                Kxy[i] = pack2(K[i].x, K[i].y); Kzw[i] = pack2(K[i].z, K[i].w);
                Vxy[i] = pack2(V[i].x, V[i].y); Vzw[i] = pack2(V[i].z, V[i].w);
            }
            #pragma unroll
            for (int i = 0; i < 4; i++)
                #pragma unroll
                for (int j = 0; j < 4; j++) {
                    fma2(a2[i * 4 + j], Kxy[i], Vxy[j]);
                    fma2(a2[i * 4 + j], Kzw[i], Vzw[j]);
                }
            float s[16];
            #pragma unroll
            for (int m = 0; m < 16; m++) {
                float2 v = unpack2(a2[m]);
                s[m] = v.x + v.y;
            }
            // value-halving butterfly: 8+4+2+1 shfl + final pair add = 16
            {
                bool up;
                up = (lane & 16);
                #pragma unroll
                for (int i = 0; i < 8; i++) {
                    float send = up ? s[i] : s[i + 8];
                    float got = __shfl_xor_sync(0xffffffffu, send, 16);
                    s[i] = (up ? s[i + 8] : s[i]) + got;
                }
                up = (lane & 8);
                #pragma unroll
                for (int i = 0; i < 4; i++) {
                    float send = up ? s[i] : s[i + 4];
                    float got = __shfl_xor_sync(0xffffffffu, send, 8);
                    s[i] = (up ? s[i + 4] : s[i]) + got;
                }
                up = (lane & 4);
                #pragma unroll
                for (int i = 0; i < 2; i++) {
                    float send = up ? s[i] : s[i + 2];
                    float got = __shfl_xor_sync(0xffffffffu, send, 4);
                    s[i] = (up ? s[i + 2] : s[i]) + got;
                }
                {
                    bool u2 = (lane & 2);
                    float send = u2 ? s[0] : s[1];
                    float got = __shfl_xor_sync(0xffffffffu, send, 2);
                    s[0] = (u2 ? s[1] : s[0]) + got;
                }
                s[0] += __shfl_xor_sync(0xffffffffu, s[0], 1);
            }
            // cell owned by this lane (even lanes write)
            if (!(lane & 1)) {
                int m = (((lane >> 4) & 1) << 3) | (((lane >> 3) & 1) << 2) |
                        (((lane >> 2) & 1) << 1) | ((lane >> 1) & 1);
                int i = m >> 2, j = m & 3;
                po[h * 144 + (db * 4 + i) * 12 + eb * 4 + j] = s[0];
            }
        } else {
            int ci = task - 72;     // ci 0..23: channels ci*4 .. ci*4+3
            float a[4];
            #pragma unroll
            for (int i = 0; i < 4; i++) {
                float4 K = ((const float4*)(sK + (ci * 4 + i) * RSK))[lane];
                a[i] = K.x + K.y + K.z + K.w;
            }
            // butterfly: 2+1 halving shfls + 3 plain = 6
            {
                bool up = (lane & 16);
                #pragma unroll
                for (int i = 0; i < 2; i++) {
                    float send = up ? a[i] : a[i + 2];
                    float got = __shfl_xor_sync(0xffffffffu, send, 16);
                    a[i] = (up ? a[i + 2] : a[i]) + got;
                }
                bool u8 = (lane & 8);
                {
                    float send = u8 ? a[0] : a[1];
                    float got = __shfl_xor_sync(0xffffffffu, send, 8);
                    a[0] = (u8 ? a[1] : a[0]) + got;
                }
                a[0] += __shfl_xor_sync(0xffffffffu, a[0], 4);
                a[0] += __shfl_xor_sync(0xffffffffu, a[0], 2);
                a[0] += __shfl_xor_sync(0xffffffffu, a[0], 1);
            }
            if (!(lane & 7)) {
                int cell = (((lane >> 4) & 1) << 1) | ((lane >> 3) & 1);
                po[1152 + ci * 4 + cell] = a[0];
            }
        }
    }
}

// ===== stage-1 reduce: 32 segments of 32 tiles per batch =====
__global__ void red1_kernel()
{
    int idx = blockIdx.x * 256 + threadIdx.x;
    int b = blockIdx.y, seg = blockIdx.z;
    if (idx >= NPART) return;
    float a = 0.f;
    const float* p = g_partial +
        ((size_t)b * NTILE + (size_t)seg * (NTILE / NSEG)) * NPART + idx;
    #pragma unroll 8
    for (int t = 0; t < NTILE / NSEG; t++) a += p[(size_t)t * NPART];
    g_red1[(seg * BB + b) * NPART + idx] = a;
}

// ===== stage-2 reduce (fixed order) =====
__global__ void red2_kernel()
{
    int gid = blockIdx.x * 256 + threadIdx.x;
    if (gid >= BB * NPART) return;
    int b = gid / NPART, idx = gid - b * NPART;
    float a = 0.f;
    #pragma unroll
    for (int s = 0; s < NSEG; s++) a += g_red1[(s * BB + b) * NPART + idx];
    g_red[gid] = a;
}

// ===== WC^T fold =====
__global__ void ctx2_kernel(const float* __restrict__ Wproj)
{
    int gid = blockIdx.x * 256 + threadIdx.x;
    if (gid >= BB * 9216) return;
    int b = gid / 9216;
    int r = gid - b * 9216;
    int o = r / 96, cp = r - o * 96;
    int h = cp / 12;
    const float* kv = g_red + b * NPART + h * 144 + (cp - h * 12) * 12;
    const float* wp = Wproj + o * 96 + h * 12;
    float a = 0.f;
    #pragma unroll
    for (int e = 0; e < 12; e++) a += wp[e] * kv[e];
    g_WCt[(b * 96 + cp) * 96 + o] = a / g_red[b * NPART + 1152 + cp];
}

// =====================================================================
// Kernel C (= R13): 256 thr, 2 CTAs/SM. stage x + Wq -> q GEMM (24 accs)
// -> reload sW=WCt + softmax -> p in-place -> WC GEMM -> out.
// =====================================================================
__global__ void __launch_bounds__(256, 2)
out2_kernel(const float* __restrict__ x, const float* __restrict__ Wq,
            float* __restrict__ out)
{
    extern __shared__ float sm[];
    float* sX = sm;                 // [96][RSO]: x, then p in-place
    float* sW = sX + 96 * RSO;      // [96][WS]: Wq, then WCt

    const int tile = blockIdx.x;
    const int b    = tile >> 10;
    const int n0   = (tile & (NTILE - 1)) * TN;
    const int tid  = threadIdx.x;
    const int tg   = tid & 31;
    const int og   = tid >> 5;
    const int nt   = tg * 4;

    const float* xb = x + (size_t)b * CCH * NTOK + n0;
    for (int i = tid; i < CCH * (TN / 4); i += 256) {
        int c = i >> 5, n4 = i & 31;
        ((float4*)(sX + c * RSO))[n4] = ((const float4*)(xb + (size_t)c * NTOK))[n4];
    }
    for (int i = tid; i < CCH * CCH; i += 256) {
        int o = i / 96, c = i - o * 96;
        sW[c * WS + o] = Wq[i];
    }
    __syncthreads();

    ull aq[24];
    #pragma unroll
    for (int j = 0; j < 24; j++) aq[j] = 0ull;
    #pragma unroll 2
    for (int c = 0; c < 96; c++) {
        float4 xv = *(const float4*)(sX + c * RSO + nt);
        ull x0 = pack2(xv.x, xv.x), x1 = pack2(xv.y, xv.y);
        ull x2 = pack2(xv.z, xv.z), x3 = pack2(xv.w, xv.w);
        const ulonglong2* w4 = (const ulonglong2*)(sW + c * WS + og * 12);
        #pragma unroll
        for (int jj = 0; jj < 3; jj++) {
            ulonglong2 w = w4[jj];
            fma2(aq[jj * 8 + 0], w.x, x0); fma2(aq[jj * 8 + 1], w.x, x1);
            fma2(aq[jj * 8 + 2], w.x, x2); fma2(aq[jj * 8 + 3], w.x, x3);
            fma2(aq[jj * 8 + 4], w.y, x0); fma2(aq[jj * 8 + 5], w.y, x1);
            fma2(aq[jj * 8 + 6], w.y, x2); fma2(aq[jj * 8 + 7], w.y, x3);
        }
    }
    __syncthreads();    // all reads of x (sX) and Wq (sW) complete

    const float* wct = g_WCt + b * 9216;
    for (int i = tid; i < CCH * CCH; i += 256) {
        int cp = i / 96, o = i - cp * 96;
        sW[cp * WS + o] = wct[i];
    }

    #pragma unroll
    for (int t = 0; t < 4; t++) {
        float qv[12];
        #pragma unroll
        for (int jj = 0; jj < 3; jj++)
            #pragma unroll
            for (int s = 0; s < 2; s++) {
                float2 v = unpack2(aq[jj * 8 + s * 4 + t]);
                qv[jj * 4 + s * 2]     = v.x;
                qv[jj * 4 + s * 2 + 1] = v.y;
            }
        float m = qv[0];
        #pragma unroll
        for (int i = 1; i < 12; i++) m = fmaxf(m, qv[i]);
        float p[12]; float sum = 0.f;
        #pragma unroll
        for (int i = 0; i < 12; i++) { p[i] = __expf(qv[i] - m); sum += p[i]; }
        float inv = 1.f / sum;
        #pragma unroll
        for (int i = 0; i < 12; i++)
            sX[(og * 12 + i) * RSO + nt + t] = p[i] * inv;
    }
    __syncthreads();    // p tile + WCt load complete

    ull ap[24];
    #pragma unroll
    for (int j = 0; j < 24; j++) ap[j] = 0ull;
    #pragma unroll 2
    for (int c = 0; c < 96; c++) {
        float4 pv = *(const float4*)(sX + c * RSO + nt);
        ull x0 = pack2(pv.x, pv.x), x1 = pack2(pv.y, pv.y);
        ull x2 = pack2(pv.z, pv.z), x3 = pack2(pv.w, pv.w);
        const ulonglong2* w4 = (const ulonglong2*)(sW + c * WS + og * 12);
        #pragma unroll
        for (int jj = 0; jj < 3; jj++) {
            ulonglong2 w = w4[jj];
            fma2(ap[jj * 8 + 0], w.x, x0); fma2(ap[jj * 8 + 1], w.x, x1);
            fma2(ap[jj * 8 + 2], w.x, x2); fma2(ap[jj * 8 + 3], w.x, x3);
            fma2(ap[jj * 8 + 4], w.y, x0); fma2(ap[jj * 8 + 5], w.y, x1);
            fma2(ap[jj * 8 + 6], w.y, x2); fma2(ap[jj * 8 + 7], w.y, x3);
        }
    }

    float* ob = out + (size_t)b * CCH * NTOK + n0 + nt;
    #pragma unroll
    for (int jj = 0; jj < 3; jj++)
        #pragma unroll
        for (int s = 0; s < 2; s++) {
            float2 v0 = unpack2(ap[jj * 8 + s * 4 + 0]);
            float2 v1 = unpack2(ap[jj * 8 + s * 4 + 1]);
            float2 v2 = unpack2(ap[jj * 8 + s * 4 + 2]);
            float2 v3 = unpack2(ap[jj * 8 + s * 4 + 3]);
            int o = og * 12 + jj * 4 + s * 2;
            *(float4*)(ob + (size_t)o * NTOK)       = make_float4(v0.x, v1.x, v2.x, v3.x);
            *(float4*)(ob + (size_t)(o + 1) * NTOK) = make_float4(v0.y, v1.y, v2.y, v3.y);
        }
}

extern "C" void kernel_launch(void* const* d_in, const int* in_sizes, int n_in,
                              void* d_out, int out_size)
{
    const float* x  = (const float*)d_in[0];
    const float* Wq = (const float*)d_in[1];
    const float* Wk = (const float*)d_in[2];
    const float* Wv = (const float*)d_in[3];
    const float* Wp = (const float*)d_in[4];
    float* out = (float*)d_out;

    const size_t smA = (size_t)(3 * 96 * RSK + 2 * 96 * WS) * sizeof(float);   // 224,256 B
    const size_t smC = (size_t)(96 * RSO + 96 * WS) * sizeof(float);           //  89,088 B
    cudaFuncSetAttribute(kv_kernel,   cudaFuncAttributeMaxDynamicSharedMemorySize, (int)smA);
    cudaFuncSetAttribute(out2_kernel, cudaFuncAttributeMaxDynamicSharedMemorySize, (int)smC);

    // keep kv_kernel in the profiler's launch slot (#4)
    noop_kernel<<<1, 32>>>();
    noop_kernel<<<1, 32>>>();
    noop_kernel<<<1, 32>>>();
    kv_kernel<<<NBLK, 512, smA>>>(x, Wk, Wv);
    red1_kernel<<<dim3(5, BB, NSEG), 256>>>();
    red2_kernel<<<(BB * NPART + 255) / 256, 256>>>();
    ctx2_kernel<<<(BB * 9216 + 255) / 256, 256>>>(Wp);
    out2_kernel<<<NBLK, 256, smC>>>(x, Wq, out);
}